// round 3
// baseline (speedup 1.0000x reference)
#include <cuda_runtime.h>

// ComplexityAnalyzer: per-image 64-bin histogram + L1 normalize + 64->32->128 MLP.
// Inputs (metadata order): grad_map [B*512*512] f32, W1 [32*64], b1 [32],
//                          W2 [128*32], b2 [128]. Output: [B*128] f32.
//
// Strategy: flat decomposition over all images so ALL 148 SMs work (grid=296,
// 2 CTAs/SM, single wave). Per-warp smem histograms -> global per-image
// histogram via atomics -> last-contributor CTA runs the tiny MLP and zeroes
// the scratch (keeps graph replays deterministic; __device__ globals start 0).

#define THREADS     512
#define WARPS       16
#define NPAD        66            // 65 live bins (0..63 + catch 64), padded
#define F4_PER_IMG  65536         // 512*512/4
#define MAX_IMG     256

__device__ unsigned int g_hist[MAX_IMG * 64];   // zero-init; self-cleaning
__device__ unsigned int g_done[MAX_IMG];        // zero-init; self-cleaning

__global__ __launch_bounds__(THREADS, 2)
void ca_hist_mlp_kernel(const float* __restrict__ grad,
                        const float* __restrict__ W1, const float* __restrict__ b1,
                        const float* __restrict__ W2, const float* __restrict__ b2,
                        float* __restrict__ out, int totalF4)
{
    __shared__ unsigned int hist[WARPS * NPAD];   // 4224 B
    __shared__ float fh[64];
    __shared__ float hmid[32];
    __shared__ float inv_s;
    __shared__ int do_mlp;

    const int tid = threadIdx.x;
    const int wid = tid >> 5;

    const int chunk = (totalF4 + gridDim.x - 1) / gridDim.x;
    int start = blockIdx.x * chunk;
    int end   = min(start + chunk, totalF4);

    const float4* src = (const float4*)grad;
    const float scale = 64.0f / 255.0f;
    const float magic = 8388608.0f;  // 2^23

    while (start < end) {
        const int img    = start / F4_PER_IMG;
        const int segEnd = min(end, (img + 1) * F4_PER_IMG);
        const int segLen = segEnd - start;

        // Zero per-warp histograms
        #pragma unroll
        for (int i = tid; i < WARPS * NPAD; i += THREADS)
            hist[i] = 0u;
        __syncthreads();

        unsigned int* myh = hist + wid * NPAD;

        #pragma unroll 4
        for (int i = start + tid; i < segEnd; i += THREADS) {
            float4 v = __ldcs(&src[i]);
            float p0, p1, p2, p3;
            // fma.rz: product + 2^23, truncate -> low mantissa = floor(v*scale)
            asm("fma.rz.f32 %0, %1, %2, %3;" : "=f"(p0) : "f"(v.x), "f"(scale), "f"(magic));
            asm("fma.rz.f32 %0, %1, %2, %3;" : "=f"(p1) : "f"(v.y), "f"(scale), "f"(magic));
            asm("fma.rz.f32 %0, %1, %2, %3;" : "=f"(p2) : "f"(v.z), "f"(scale), "f"(magic));
            asm("fma.rz.f32 %0, %1, %2, %3;" : "=f"(p3) : "f"(v.w), "f"(scale), "f"(magic));
            unsigned i0 = min(__float_as_uint(p0) & 0x7Fu, 64u);
            unsigned i1 = min(__float_as_uint(p1) & 0x7Fu, 64u);
            unsigned i2 = min(__float_as_uint(p2) & 0x7Fu, 64u);
            unsigned i3 = min(__float_as_uint(p3) & 0x7Fu, 64u);
            atomicAdd(&myh[i0], 1u);
            atomicAdd(&myh[i1], 1u);
            atomicAdd(&myh[i2], 1u);
            atomicAdd(&myh[i3], 1u);
        }
        __syncthreads();

        // Reduce warp hists -> 64 bins, flush to global (fold catch bin 64 into 63)
        if (tid < 64) {
            unsigned s = 0;
            #pragma unroll
            for (int w = 0; w < WARPS; ++w)
                s += hist[w * NPAD + tid];
            if (tid == 63) {
                #pragma unroll
                for (int w = 0; w < WARPS; ++w)
                    s += hist[w * NPAD + 64];
            }
            if (s) atomicAdd(&g_hist[img * 64 + tid], s);
            __threadfence();   // release our contribution before the done-count
        }
        __syncthreads();

        if (tid == 0) {
            unsigned old = atomicAdd(&g_done[img], (unsigned)segLen);
            do_mlp = (old + (unsigned)segLen == (unsigned)F4_PER_IMG);
        }
        __syncthreads();

        if (do_mlp) {
            // Acquire + coherent read of the completed histogram
            if (tid < 64) {
                __threadfence();
                fh[tid] = (float)atomicAdd(&g_hist[img * 64 + tid], 0u);
            }
            __syncthreads();

            if (tid < 32) {
                float s = fh[tid] + fh[tid + 32];
                #pragma unroll
                for (int off = 16; off > 0; off >>= 1)
                    s += __shfl_down_sync(0xFFFFFFFFu, s, off);
                if (tid == 0) inv_s = 1.0f / fmaxf(s, 1e-12f);
            }
            __syncthreads();
            if (tid < 64) fh[tid] *= inv_s;
            __syncthreads();

            // Layer 1: 64 -> 32 with ReLU
            if (tid < 32) {
                float acc = b1[tid];
                const float* w = W1 + tid * 64;
                #pragma unroll
                for (int b = 0; b < 64; ++b) acc = fmaf(fh[b], w[b], acc);
                hmid[tid] = fmaxf(acc, 0.0f);
            }
            __syncthreads();

            // Layer 2: 32 -> 128
            if (tid < 128) {
                float acc = b2[tid];
                const float* w = W2 + tid * 32;
                #pragma unroll
                for (int j = 0; j < 32; ++j) acc = fmaf(hmid[j], w[j], acc);
                out[img * 128 + tid] = acc;
            }

            // Self-clean scratch for deterministic graph replays
            if (tid < 64) atomicExch(&g_hist[img * 64 + tid], 0u);
            if (tid == 0) atomicExch(&g_done[img], 0u);
            __syncthreads();
        }

        start = segEnd;
    }
}

extern "C" void kernel_launch(void* const* d_in, const int* in_sizes, int n_in,
                              void* d_out, int out_size) {
    const float* grad = (const float*)d_in[0];
    const float* W1   = (const float*)d_in[1];
    const float* b1   = (const float*)d_in[2];
    const float* W2   = (const float*)d_in[3];
    const float* b2   = (const float*)d_in[4];
    float* out = (float*)d_out;

    int totalF4 = in_sizes[0] / 4;               // float4 count
    int grid = 296;                              // 2 * 148 SMs, single resident wave
    ca_hist_mlp_kernel<<<grid, THREADS>>>(grad, W1, b1, W2, b2, out, totalF4);
}

// round 4
// speedup vs baseline: 1.0750x; 1.0750x over previous
#include <cuda_runtime.h>

// ComplexityAnalyzer: per-image 64-bin histogram + L1 normalize + 64->32->128 MLP.
// Inputs (metadata order): grad_map [B*512*512] f32, W1 [32*64], b1 [32],
//                          W2 [128*32], b2 [128]. Output: [B*128] f32.
//
// R4: R2's fast microstructure (1024-thread CTA, __ldg, affine unroll-4 loop)
// + flat partition over 148 CTAs in 1024-float4 block units (image boundaries
// are block-aligned -> <=2 segments/CTA, each a fixed-stride affine loop).
// Per-image completion via global counter; finishing CTA runs the MLP and
// zeroes the scratch (deterministic across graph replays).

#define THREADS     1024
#define WARPS       32
#define NPAD        66            // 65 live bins (0..63 + catch 64), padded
#define BLK_F4      1024          // float4s per work block (1 per thread)
#define BLKS_PER_IMG 64           // 65536 F4 / 1024
#define MAX_IMG     256

__device__ unsigned int g_hist[MAX_IMG * 64];   // zero-init; self-cleaning
__device__ unsigned int g_done[MAX_IMG];        // zero-init; self-cleaning

__global__ __launch_bounds__(THREADS, 1)
void ca_hist_mlp_kernel(const float* __restrict__ grad,
                        const float* __restrict__ W1, const float* __restrict__ b1,
                        const float* __restrict__ W2, const float* __restrict__ b2,
                        float* __restrict__ out, int totalBlocks)
{
    __shared__ unsigned int hist[WARPS * NPAD];   // 8448 B
    __shared__ float fh[64];
    __shared__ float hmid[32];
    __shared__ float inv_s;
    __shared__ int do_mlp;

    const int tid = threadIdx.x;
    const int wid = tid >> 5;

    // Flat partition in block units: CTA i gets base + (i < rem) blocks.
    const int nCta = gridDim.x;
    const int base = totalBlocks / nCta;
    const int rem  = totalBlocks % nCta;
    int b0 = blockIdx.x * base + min((int)blockIdx.x, rem);
    int bEnd = b0 + base + (blockIdx.x < rem ? 1 : 0);

    const float4* src = (const float4*)grad;
    const float scale = 64.0f / 255.0f;
    const float magic = 8388608.0f;  // 2^23

    while (b0 < bEnd) {
        const int img   = b0 / BLKS_PER_IMG;
        const int bSeg  = min(bEnd, (img + 1) * BLKS_PER_IMG);
        const int nBlk  = bSeg - b0;

        // Zero per-warp histograms
        #pragma unroll
        for (int i = tid; i < WARPS * NPAD; i += THREADS)
            hist[i] = 0u;
        __syncthreads();

        unsigned int* myh = hist + wid * NPAD;
        const float4* p = src + (size_t)b0 * BLK_F4 + tid;

        #pragma unroll 4
        for (int it = 0; it < nBlk; ++it) {
            float4 v = __ldg(&p[it * BLK_F4]);
            float p0, p1, p2, p3;
            // fma.rz: product + 2^23, truncate -> low mantissa = floor(v*scale)
            asm("fma.rz.f32 %0, %1, %2, %3;" : "=f"(p0) : "f"(v.x), "f"(scale), "f"(magic));
            asm("fma.rz.f32 %0, %1, %2, %3;" : "=f"(p1) : "f"(v.y), "f"(scale), "f"(magic));
            asm("fma.rz.f32 %0, %1, %2, %3;" : "=f"(p2) : "f"(v.z), "f"(scale), "f"(magic));
            asm("fma.rz.f32 %0, %1, %2, %3;" : "=f"(p3) : "f"(v.w), "f"(scale), "f"(magic));
            unsigned i0 = min(__float_as_uint(p0) & 0x7Fu, 64u);
            unsigned i1 = min(__float_as_uint(p1) & 0x7Fu, 64u);
            unsigned i2 = min(__float_as_uint(p2) & 0x7Fu, 64u);
            unsigned i3 = min(__float_as_uint(p3) & 0x7Fu, 64u);
            atomicAdd(&myh[i0], 1u);
            atomicAdd(&myh[i1], 1u);
            atomicAdd(&myh[i2], 1u);
            atomicAdd(&myh[i3], 1u);
        }
        __syncthreads();

        // Reduce warp hists -> 64 bins, flush to global (fold catch bin 64 into 63)
        if (tid < 64) {
            unsigned s = 0;
            #pragma unroll
            for (int w = 0; w < WARPS; ++w)
                s += hist[w * NPAD + tid];
            if (tid == 63) {
                #pragma unroll
                for (int w = 0; w < WARPS; ++w)
                    s += hist[w * NPAD + 64];
            }
            if (s) atomicAdd(&g_hist[img * 64 + tid], s);
            __threadfence();   // release our contribution before the done-count
        }
        __syncthreads();

        if (tid == 0) {
            unsigned old = atomicAdd(&g_done[img], (unsigned)nBlk);
            do_mlp = (old + (unsigned)nBlk == (unsigned)BLKS_PER_IMG);
        }
        __syncthreads();

        if (do_mlp) {
            // Acquire + coherent read of the completed histogram
            if (tid < 64) {
                __threadfence();
                fh[tid] = (float)atomicAdd(&g_hist[img * 64 + tid], 0u);
            }
            __syncthreads();

            if (tid < 32) {
                float s = fh[tid] + fh[tid + 32];
                #pragma unroll
                for (int off = 16; off > 0; off >>= 1)
                    s += __shfl_down_sync(0xFFFFFFFFu, s, off);
                if (tid == 0) inv_s = 1.0f / fmaxf(s, 1e-12f);
            }
            __syncthreads();
            if (tid < 64) fh[tid] *= inv_s;
            __syncthreads();

            // Layer 1: 64 -> 32 with ReLU
            if (tid < 32) {
                float acc = b1[tid];
                const float* w = W1 + tid * 64;
                #pragma unroll
                for (int b = 0; b < 64; ++b) acc = fmaf(fh[b], w[b], acc);
                hmid[tid] = fmaxf(acc, 0.0f);
            }
            __syncthreads();

            // Layer 2: 32 -> 128
            if (tid < 128) {
                float acc = b2[tid];
                const float* w = W2 + tid * 32;
                #pragma unroll
                for (int j = 0; j < 32; ++j) acc = fmaf(hmid[j], w[j], acc);
                out[img * 128 + tid] = acc;
            }

            // Self-clean scratch for deterministic graph replays
            if (tid < 64) atomicExch(&g_hist[img * 64 + tid], 0u);
            if (tid == 0) atomicExch(&g_done[img], 0u);
            __syncthreads();
        }

        b0 = bSeg;
    }
}

extern "C" void kernel_launch(void* const* d_in, const int* in_sizes, int n_in,
                              void* d_out, int out_size) {
    const float* grad = (const float*)d_in[0];
    const float* W1   = (const float*)d_in[1];
    const float* b1   = (const float*)d_in[2];
    const float* W2   = (const float*)d_in[3];
    const float* b2   = (const float*)d_in[4];
    float* out = (float*)d_out;

    int totalBlocks = in_sizes[0] / (4 * BLK_F4);   // 1024-float4 blocks
    ca_hist_mlp_kernel<<<148, THREADS>>>(grad, W1, b1, W2, b2, out, totalBlocks);
}

// round 5
// speedup vs baseline: 1.1455x; 1.0656x over previous
#include <cuda_runtime.h>

// ComplexityAnalyzer: per-image 64-bin histogram + L1 normalize + 64->32->128 MLP.
// Inputs (metadata order): grad_map [B*512*512] f32, W1 [32*64], b1 [32],
//                          W2 [128*32], b2 [128]. Output: [B*128] f32.
//
// R5: R2's per-image-CTA shape (grid=B, 1024 thr, static 64-iter loop) with a
// 4-stage cp.async.cg smem pipeline to decouple DRAM latency from the 64-reg
// cap. Each thread owns one 16B slot per stage; no mainloop syncs needed.

#define THREADS 1024
#define WARPS   32
#define NPAD    66           // 65 live bins (0..63 + catch bin 64), padded
#define STAGES  4
#define ITERS   64           // 512*512/4 float4 / 1024 threads

__device__ __forceinline__ void cp_async16(unsigned smem_addr, const void* gptr) {
    asm volatile("cp.async.cg.shared.global [%0], [%1], 16;\n"
                 :: "r"(smem_addr), "l"(gptr) : "memory");
}
__device__ __forceinline__ void cp_commit() {
    asm volatile("cp.async.commit_group;\n" ::: "memory");
}
template <int N>
__device__ __forceinline__ void cp_wait() {
    asm volatile("cp.async.wait_group %0;\n" :: "n"(N) : "memory");
}

__global__ __launch_bounds__(THREADS, 1)
void ca_hist_mlp_kernel(const float* __restrict__ grad,
                        const float* __restrict__ W1, const float* __restrict__ b1,
                        const float* __restrict__ W2, const float* __restrict__ b2,
                        float* __restrict__ out)
{
    __shared__ float4 stage[STAGES][THREADS];      // 64 KB streaming buffers
    __shared__ unsigned int hist[WARPS * NPAD];    // 8448 B
    __shared__ float fh[64];
    __shared__ float hmid[32];
    __shared__ float inv_s;

    const int tid = threadIdx.x;
    const int wid = tid >> 5;
    const int img = blockIdx.x;

    // Zero per-warp histograms
    #pragma unroll
    for (int i = tid; i < WARPS * NPAD; i += THREADS)
        hist[i] = 0u;
    __syncthreads();

    unsigned int* myh = hist + wid * NPAD;
    const float4* src = (const float4*)(grad + (size_t)img * 262144u) + tid;

    unsigned slot[STAGES];
    #pragma unroll
    for (int s = 0; s < STAGES; ++s)
        slot[s] = (unsigned)__cvta_generic_to_shared(&stage[s][tid]);

    const float scale = 64.0f / 255.0f;
    const float magic = 8388608.0f;  // 2^23

    // Prologue: fill all stages
    #pragma unroll
    for (int s = 0; s < STAGES; ++s) {
        cp_async16(slot[s], src + s * THREADS);
        cp_commit();
    }

    #define PROCESS(v)                                                              \
        do {                                                                        \
            float q0, q1, q2, q3;                                                   \
            asm("fma.rz.f32 %0, %1, %2, %3;" : "=f"(q0) : "f"((v).x), "f"(scale), "f"(magic)); \
            asm("fma.rz.f32 %0, %1, %2, %3;" : "=f"(q1) : "f"((v).y), "f"(scale), "f"(magic)); \
            asm("fma.rz.f32 %0, %1, %2, %3;" : "=f"(q2) : "f"((v).z), "f"(scale), "f"(magic)); \
            asm("fma.rz.f32 %0, %1, %2, %3;" : "=f"(q3) : "f"((v).w), "f"(scale), "f"(magic)); \
            unsigned i0 = min(__float_as_uint(q0) & 0x7Fu, 64u);                    \
            unsigned i1 = min(__float_as_uint(q1) & 0x7Fu, 64u);                    \
            unsigned i2 = min(__float_as_uint(q2) & 0x7Fu, 64u);                    \
            unsigned i3 = min(__float_as_uint(q3) & 0x7Fu, 64u);                    \
            atomicAdd(&myh[i0], 1u);                                                \
            atomicAdd(&myh[i1], 1u);                                                \
            atomicAdd(&myh[i2], 1u);                                                \
            atomicAdd(&myh[i3], 1u);                                                \
        } while (0)

    // Main loop: consume stage i, refill with block i+STAGES
    #pragma unroll 4
    for (int i = 0; i < ITERS - STAGES; ++i) {
        cp_wait<STAGES - 1>();                 // stage (i % STAGES) is ready
        float4 v = stage[i & (STAGES - 1)][tid];
        PROCESS(v);
        cp_async16(slot[i & (STAGES - 1)], src + (i + STAGES) * THREADS);
        cp_commit();
    }
    // Tail: drain remaining stages
    cp_wait<0>();
    #pragma unroll
    for (int i = ITERS - STAGES; i < ITERS; ++i) {
        float4 v = stage[i & (STAGES - 1)][tid];
        PROCESS(v);
    }
    __syncthreads();

    // Reduce warp hists -> 64 bins (fold catch bin 64 into 63: histc puts v==VMAX last)
    if (tid < 64) {
        unsigned s = 0;
        #pragma unroll
        for (int w = 0; w < WARPS; ++w)
            s += hist[w * NPAD + tid];
        if (tid == 63) {
            #pragma unroll
            for (int w = 0; w < WARPS; ++w)
                s += hist[w * NPAD + 64];
        }
        fh[tid] = (float)s;
    }
    __syncthreads();

    // L1 norm denominator
    if (tid < 32) {
        float s = fh[tid] + fh[tid + 32];
        #pragma unroll
        for (int off = 16; off > 0; off >>= 1)
            s += __shfl_down_sync(0xFFFFFFFFu, s, off);
        if (tid == 0) inv_s = 1.0f / fmaxf(s, 1e-12f);
    }
    __syncthreads();
    if (tid < 64) fh[tid] *= inv_s;
    __syncthreads();

    // Layer 1: 64 -> 32 with ReLU
    if (tid < 32) {
        float acc = b1[tid];
        const float* w = W1 + tid * 64;
        #pragma unroll
        for (int b = 0; b < 64; ++b) acc = fmaf(fh[b], w[b], acc);
        hmid[tid] = fmaxf(acc, 0.0f);
    }
    __syncthreads();

    // Layer 2: 32 -> 128
    if (tid < 128) {
        float acc = b2[tid];
        const float* w = W2 + tid * 32;
        #pragma unroll
        for (int j = 0; j < 32; ++j) acc = fmaf(hmid[j], w[j], acc);
        out[img * 128 + tid] = acc;
    }
}

extern "C" void kernel_launch(void* const* d_in, const int* in_sizes, int n_in,
                              void* d_out, int out_size) {
    const float* grad = (const float*)d_in[0];
    const float* W1   = (const float*)d_in[1];
    const float* b1   = (const float*)d_in[2];
    const float* W2   = (const float*)d_in[3];
    const float* b2   = (const float*)d_in[4];
    float* out = (float*)d_out;

    int B = in_sizes[0] / (512 * 512);
    ca_hist_mlp_kernel<<<B, THREADS>>>(grad, W1, b1, W2, b2, out);
}